// round 9
// baseline (speedup 1.0000x reference)
#include <cuda_runtime.h>
#include <cstdint>

#define NBATCH 256
#define NN     64
#define DT     4096
#define THREADS 256

__device__ float e_scratch[NBATCH * NN];   // row variances (K1a -> K1b)

// ---------------------------------------------------------------------------
// tf32 helpers (plain PTX, valid on .target sm_103 — no tcgen05 anywhere)
// ---------------------------------------------------------------------------
__device__ __forceinline__ uint32_t f2tf32(float f) {
    uint32_t r;
    asm("cvt.rna.tf32.f32 %0, %1;" : "=r"(r) : "f"(f));
    return r;
}
__device__ __forceinline__ void mma_tf32(float& c0, float& c1, float& c2, float& c3,
                                         uint32_t a0, uint32_t a1, uint32_t a2, uint32_t a3,
                                         uint32_t b0, uint32_t b1) {
    asm volatile(
        "mma.sync.aligned.m16n8k8.row.col.f32.tf32.tf32.f32 "
        "{%0,%1,%2,%3}, {%4,%5,%6,%7}, {%8,%9}, {%0,%1,%2,%3};"
        : "+f"(c0), "+f"(c1), "+f"(c2), "+f"(c3)
        : "r"(a0), "r"(a1), "r"(a2), "r"(a3), "r"(b0), "r"(b1));
}

// ============================================================================
// K1a: row variances (ddof=1). 1024 blocks = (batch, 16-row group).
// ============================================================================
__global__ void __launch_bounds__(THREADS, 4)
dga_var(const float* __restrict__ x)
{
    const int b    = blockIdx.x >> 2;
    const int g    = blockIdx.x & 3;
    const int tid  = threadIdx.x;
    const int warp = tid >> 5;
    const int lane = tid & 31;
    const float* xb = x + (size_t)b * NN * DT;

    const int r0 = g * 16 + warp * 2;
    const float4* rowA = (const float4*)(xb + (size_t)r0 * DT);
    const float4* rowB = (const float4*)(xb + (size_t)(r0 + 1) * DT);
    float sA = 0.f, ssA = 0.f, sB = 0.f, ssB = 0.f;
    #pragma unroll
    for (int k = 0; k < 32; ++k) {
        float4 a = rowA[lane + 32 * k];
        float4 c = rowB[lane + 32 * k];
        sA  += (a.x + a.y) + (a.z + a.w);
        ssA += a.x * a.x + a.y * a.y + a.z * a.z + a.w * a.w;
        sB  += (c.x + c.y) + (c.z + c.w);
        ssB += c.x * c.x + c.y * c.y + c.z * c.z + c.w * c.w;
    }
    #pragma unroll
    for (int m = 16; m; m >>= 1) {
        sA  += __shfl_xor_sync(0xffffffffu, sA,  m);
        ssA += __shfl_xor_sync(0xffffffffu, ssA, m);
        sB  += __shfl_xor_sync(0xffffffffu, sB,  m);
        ssB += __shfl_xor_sync(0xffffffffu, ssB, m);
    }
    if (lane == 0) {
        float meanA = sA * (1.0f / DT);
        float meanB = sB * (1.0f / DT);
        e_scratch[b * NN + r0]     = (ssA - sA * meanA) * (1.0f / (DT - 1));
        e_scratch[b * NN + r0 + 1] = (ssB - sB * meanB) * (1.0f / (DT - 1));
    }
}

// ============================================================================
// K1b: 4 scalar coefs -> masked softmax -> attn_weights. 256 blocks.
// ============================================================================
__global__ void __launch_bounds__(THREADS)
dga_weights(const float* __restrict__ wq, const float* __restrict__ bq,
            const float* __restrict__ wk, const float* __restrict__ bk,
            float* __restrict__ attn)
{
    __shared__ float e_sm[NN];
    __shared__ float coef[4];

    const int b   = blockIdx.x;
    const int tid = threadIdx.x;

    if (tid < NN) e_sm[tid] = e_scratch[b * NN + tid];
    if (tid == 0) {
        float A = 0.f, B = 0.f, C = 0.f, Dc = 0.f;
        #pragma unroll
        for (int h = 0; h < 16; ++h) {
            float q = wq[h], qb = bq[h], k = wk[h], kb = bk[h];
            A += q * k; B += q * kb; C += qb * k; Dc += qb * kb;
        }
        coef[0] = A; coef[1] = B; coef[2] = C; coef[3] = Dc;
    }
    __syncthreads();

    const int i  = tid >> 2;
    const int jg = tid & 3;
    const float ei = e_sm[i];
    const float m1 = 0.25f * (coef[0] * ei + coef[2]);   // SCALE = 0.25
    const float m0 = 0.25f * (coef[1] * ei + coef[3]);
    float sv[16];
    float mx = -3.4e38f;
    #pragma unroll
    for (int t = 0; t < 16; ++t) {
        int j = jg * 16 + t;
        float s = fmaf(m1, e_sm[j], m0);
        if (j == i) s = -1000000000.0f;
        sv[t] = s;
        mx = fmaxf(mx, s);
    }
    #pragma unroll
    for (int m = 1; m < 4; m <<= 1)
        mx = fmaxf(mx, __shfl_xor_sync(0xffffffffu, mx, m));
    float sum = 0.f;
    #pragma unroll
    for (int t = 0; t < 16; ++t) { sv[t] = __expf(sv[t] - mx); sum += sv[t]; }
    #pragma unroll
    for (int m = 1; m < 4; m <<= 1)
        sum += __shfl_xor_sync(0xffffffffu, sum, m);
    float inv = 1.0f / sum;

    float* arow = attn + (((size_t)b * NN) + i) * NN;
    #pragma unroll
    for (int t = 0; t < 16; ++t)
        arow[jg * 16 + t] = sv[t] * inv;
}

// ============================================================================
// K2 (mma.sync tf32, 3-product split):
//   out[i][t] = sum_j (W+I)[i][j] * x[j][t]
// Grid 512 = (batch, t-half). 8 warps = 4 m-groups x 2 n-halves.
// Per chunk of 128 t: stage X as (hi,lo) uint2; k-loop of m16n8k8 mmas.
// ============================================================================
#define TCH  128                               // t per chunk
#define WSTR 68                                // uint2 stride, W rows
#define XSTR 132                               // uint2 stride, X rows
#define SM_W_BYTES (NN * WSTR * 8)             // 34816
#define SM_X_BYTES (NN * XSTR * 8)             // 67584
#define SMEM_K2    (SM_W_BYTES + SM_X_BYTES)   // 102400

__global__ void __launch_bounds__(THREADS, 2)
dga_gemm_mma(const float* __restrict__ x, const float* __restrict__ attn,
             float* __restrict__ out)
{
    extern __shared__ char sm[];
    uint2* w2 = (uint2*)sm;                    // [i][j] -> (hi, lo) of (W+I)
    uint2* x2 = (uint2*)(sm + SM_W_BYTES);     // [j][t_local] -> (hi, lo) of x

    const int b    = blockIdx.x >> 1;
    const int half = blockIdx.x & 1;
    const int tid  = threadIdx.x;
    const int warp = tid >> 5;
    const int lane = tid & 31;
    const int g    = lane >> 2;                // mma group id (0..7)
    const int tg   = lane & 3;                 // thread in group (0..3)

    const float* xb = x    + (size_t)b * NN * DT;
    const float* ab = attn + (size_t)b * NN * NN;
    float*       ob = out  + (size_t)b * NN * DT;

    // ---- stage A = (W + I) as tf32 hi/lo ----
    #pragma unroll
    for (int s = 0; s < 16; ++s) {
        int idx = tid + 256 * s;               // 4096 elements
        int i = idx >> 6, j = idx & 63;
        float w = ab[idx] + (i == j ? 1.0f : 0.0f);
        uint32_t h = f2tf32(w);
        uint32_t l = f2tf32(w - __uint_as_float(h));
        w2[i * WSTR + j] = make_uint2(h, l);
    }

    const int mg = (warp & 3) * 16;            // this warp's 16 output rows
    const int nb = (warp >> 2) * 64;           // this warp's 64-t slice in chunk

    #pragma unroll 1
    for (int c = 0; c < 16; ++c) {
        const int t0 = half * 2048 + c * TCH;
        __syncthreads();                       // prev compute done (also covers W)

        // ---- stage X chunk: fp32 -> (hi,lo) tf32 pairs ----
        #pragma unroll
        for (int s = 0; s < 8; ++s) {
            int u = tid + 256 * s;             // 2048 float4 loads
            int j = u >> 5, q = u & 31;
            float4 v = *(const float4*)(xb + (size_t)j * DT + t0 + 4 * q);
            uint32_t h0 = f2tf32(v.x), l0 = f2tf32(v.x - __uint_as_float(h0));
            uint32_t h1 = f2tf32(v.y), l1 = f2tf32(v.y - __uint_as_float(h1));
            uint32_t h2 = f2tf32(v.z), l2 = f2tf32(v.z - __uint_as_float(h2));
            uint32_t h3 = f2tf32(v.w), l3 = f2tf32(v.w - __uint_as_float(h3));
            uint2* dst = &x2[j * XSTR + 4 * q];
            *(uint4*)(dst)     = make_uint4(h0, l0, h1, l1);
            *(uint4*)(dst + 2) = make_uint4(h2, l2, h3, l3);
        }
        __syncthreads();

        // ---- mma mainloop: C[8 tiles][4 frags] ----
        float C[8][4];
        #pragma unroll
        for (int t = 0; t < 8; ++t) { C[t][0] = C[t][1] = C[t][2] = C[t][3] = 0.f; }

        #pragma unroll
        for (int ks = 0; ks < 8; ++ks) {
            const uint2* wr = &w2[(mg + g) * WSTR + ks * 8 + tg];
            uint2 a0 = wr[0];                  // (hi,lo): row mg+g,   k ks*8+tg
            uint2 a1 = wr[8 * WSTR];           //          row +8
            uint2 a2 = wr[4];                  //          k +4
            uint2 a3 = wr[8 * WSTR + 4];
            const uint2* xr0 = &x2[(ks * 8 + tg) * XSTR + nb + g];
            const uint2* xr1 = xr0 + 4 * XSTR;
            #pragma unroll
            for (int t = 0; t < 8; ++t) {
                uint2 b0 = xr0[t * 8];
                uint2 b1 = xr1[t * 8];
                mma_tf32(C[t][0], C[t][1], C[t][2], C[t][3],
                         a0.x, a1.x, a2.x, a3.x, b0.x, b1.x);   // hi*hi
                mma_tf32(C[t][0], C[t][1], C[t][2], C[t][3],
                         a0.x, a1.x, a2.x, a3.x, b0.y, b1.y);   // hi*lo
                mma_tf32(C[t][0], C[t][1], C[t][2], C[t][3],
                         a0.y, a1.y, a2.y, a3.y, b0.x, b1.x);   // lo*hi
            }
        }

        // ---- epilogue: C frag -> out[i][t] (float2 stores, 32B sectors) ----
        #pragma unroll
        for (int t = 0; t < 8; ++t) {
            int tcol = t0 + nb + t * 8 + 2 * tg;
            *(float2*)(ob + (size_t)(mg + g)     * DT + tcol) =
                make_float2(C[t][0], C[t][1]);
            *(float2*)(ob + (size_t)(mg + g + 8) * DT + tcol) =
                make_float2(C[t][2], C[t][3]);
        }
    }
}

extern "C" void kernel_launch(void* const* d_in, const int* in_sizes, int n_in,
                              void* d_out, int out_size) {
    const float* x  = (const float*)d_in[0];
    const float* wq = (const float*)d_in[1];
    const float* bq = (const float*)d_in[2];
    const float* wk = (const float*)d_in[3];
    const float* bk = (const float*)d_in[4];
    float* out  = (float*)d_out;
    float* attn = out + (size_t)NBATCH * NN * DT;   // out tensor first, then attn

    cudaFuncSetAttribute(dga_gemm_mma, cudaFuncAttributeMaxDynamicSharedMemorySize,
                         SMEM_K2);

    dga_var<<<NBATCH * 4, THREADS>>>(x);
    dga_weights<<<NBATCH, THREADS>>>(wq, bq, wk, bk, attn);
    dga_gemm_mma<<<NBATCH * 2, THREADS, SMEM_K2>>>(x, attn, out);
}

// round 10
// speedup vs baseline: 1.9567x; 1.9567x over previous
#include <cuda_runtime.h>
#include <cstdint>

#define NBATCH 256
#define NN     64
#define DT     4096
#define THREADS 256

#define XSTR 136                       // floats; 136 % 32 == 8 -> conflict-free B loads
#define WSTR 68
#define SMF_W  0                       // w_sm: 64*68 floats           = 4352
#define SMF_X0 (SMF_W + NN * WSTR)     // x buf 0: 64*136              = 8704
#define SMF_X1 (SMF_X0 + NN * XSTR)
#define SMF_E  (SMF_X1 + NN * XSTR)    // e[64]
#define SMF_CF (SMF_E + NN)            // coef[4]
#define SMEM_FLOATS (SMF_CF + 8)
#define SMEM_BYTES  (SMEM_FLOATS * 4)  // ~87.6 KB -> 2 CTAs/SM

__device__ __forceinline__ uint32_t f2tf32(float f) {
    uint32_t r;
    asm("cvt.rna.tf32.f32 %0, %1;" : "=r"(r) : "f"(f));
    return r;
}
__device__ __forceinline__ void mma_tf32(float& c0, float& c1, float& c2, float& c3,
                                         uint32_t a0, uint32_t a1, uint32_t a2, uint32_t a3,
                                         uint32_t b0, uint32_t b1) {
    asm volatile(
        "mma.sync.aligned.m16n8k8.row.col.f32.tf32.tf32.f32 "
        "{%0,%1,%2,%3}, {%4,%5,%6,%7}, {%8,%9}, {%0,%1,%2,%3};"
        : "+f"(c0), "+f"(c1), "+f"(c2), "+f"(c3)
        : "r"(a0), "r"(a1), "r"(a2), "r"(a3), "r"(b0), "r"(b1));
}
__device__ __forceinline__ void cp_async16(void* smem_dst, const void* gsrc) {
    unsigned sa = (unsigned)__cvta_generic_to_shared(smem_dst);
    asm volatile("cp.async.cg.shared.global [%0], [%1], 16;" :: "r"(sa), "l"(gsrc));
}

// ============================================================================
// Fused: variance -> coefs -> masked softmax -> tf32 mma GEMM + fp32 residual
// Grid 256 (1 CTA per batch), 256 threads, 2 CTAs/SM.
// ============================================================================
__global__ void __launch_bounds__(THREADS, 2)
dga_fused(const float* __restrict__ x,  const float* __restrict__ wq,
          const float* __restrict__ bq, const float* __restrict__ wk,
          const float* __restrict__ bk, float* __restrict__ out,
          float* __restrict__ attn)
{
    extern __shared__ float smf[];
    float* w_sm = smf + SMF_W;
    float* e_sm = smf + SMF_E;
    float* coef = smf + SMF_CF;

    const int b    = blockIdx.x;
    const int tid  = threadIdx.x;
    const int warp = tid >> 5;
    const int lane = tid & 31;
    const float* xb = x + (size_t)b * NN * DT;
    float*       ob = out + (size_t)b * NN * DT;

    // ---- Phase 1: row variances (ddof=1). 8 warps, 8 rows each. ----
    for (int r = warp; r < NN; r += 8) {
        const float4* row = (const float4*)(xb + (size_t)r * DT);
        float s = 0.f, ss = 0.f;
        #pragma unroll
        for (int k = 0; k < 32; ++k) {
            float4 v = row[lane + 32 * k];
            s  += (v.x + v.y) + (v.z + v.w);
            ss += v.x * v.x + v.y * v.y + v.z * v.z + v.w * v.w;
        }
        #pragma unroll
        for (int m = 16; m; m >>= 1) {
            s  += __shfl_xor_sync(0xffffffffu, s,  m);
            ss += __shfl_xor_sync(0xffffffffu, ss, m);
        }
        if (lane == 0) {
            float mean = s * (1.0f / DT);
            e_sm[r] = (ss - s * mean) * (1.0f / (DT - 1));
        }
    }
    if (tid == 0) {
        float A = 0.f, B = 0.f, C = 0.f, Dc = 0.f;
        #pragma unroll
        for (int h = 0; h < 16; ++h) {
            float q = wq[h], qb = bq[h], k = wk[h], kb = bk[h];
            A += q * k; B += q * kb; C += qb * k; Dc += qb * kb;
        }
        coef[0] = A; coef[1] = B; coef[2] = C; coef[3] = Dc;
    }
    __syncthreads();

    // ---- Phase 2: masked softmax; 4 threads/row. diag weight == exactly 0 ----
    {
        const int i  = tid >> 2;
        const int jg = tid & 3;
        const float ei = e_sm[i];
        const float m1 = 0.25f * (coef[0] * ei + coef[2]);   // SCALE = 0.25
        const float m0 = 0.25f * (coef[1] * ei + coef[3]);
        float sv[16];
        float mx = -3.4e38f;
        #pragma unroll
        for (int t = 0; t < 16; ++t) {
            int j = jg * 16 + t;
            float s = fmaf(m1, e_sm[j], m0);
            if (j == i) s = -1000000000.0f;
            sv[t] = s;
            mx = fmaxf(mx, s);
        }
        #pragma unroll
        for (int m = 1; m < 4; m <<= 1)
            mx = fmaxf(mx, __shfl_xor_sync(0xffffffffu, mx, m));
        float sum = 0.f;
        #pragma unroll
        for (int t = 0; t < 16; ++t) { sv[t] = __expf(sv[t] - mx); sum += sv[t]; }
        #pragma unroll
        for (int m = 1; m < 4; m <<= 1)
            sum += __shfl_xor_sync(0xffffffffu, sum, m);
        float inv = 1.0f / sum;

        float* arow = attn + (((size_t)b * NN) + i) * NN;
        #pragma unroll
        for (int t = 0; t < 16; ++t) {
            float w = sv[t] * inv;
            arow[jg * 16 + t] = w;
            w_sm[i * WSTR + jg * 16 + t] = w;
        }
    }
    __syncthreads();

    // ---- Phase 3: preload A-fragments (W as tf32) into registers ----
    const int mw = (warp & 3) * 16;        // warp's 16 output rows
    const int nco = (warp >> 2) * 64;      // warp's 64-col slice within chunk
    const int g   = lane >> 2;
    const int tg  = lane & 3;

    uint32_t A[8][4];
    #pragma unroll
    for (int ks = 0; ks < 8; ++ks) {
        A[ks][0] = f2tf32(w_sm[(mw + g)     * WSTR + ks * 8 + tg]);
        A[ks][1] = f2tf32(w_sm[(mw + g + 8) * WSTR + ks * 8 + tg]);
        A[ks][2] = f2tf32(w_sm[(mw + g)     * WSTR + ks * 8 + tg + 4]);
        A[ks][3] = f2tf32(w_sm[(mw + g + 8) * WSTR + ks * 8 + tg + 4]);
    }

    // ---- Phase 4: GEMM, 32 chunks of 128 t, double-buffered cp.async ----
    {
        float* xbuf0 = smf + SMF_X0;
        float* xbuf1 = smf + SMF_X1;

        // prologue: stage chunk 0
        #pragma unroll
        for (int s = 0; s < 8; ++s) {
            int u = tid + 256 * s;             // 2048 x 16B
            int j = u >> 5, q = u & 31;
            cp_async16(&xbuf0[j * XSTR + q * 4], xb + (size_t)j * DT + q * 4);
        }
        asm volatile("cp.async.commit_group;");

        #pragma unroll 1
        for (int c = 0; c < 32; ++c) {
            const int t0 = c * 128;
            float* xc = (c & 1) ? xbuf1 : xbuf0;

            if (c + 1 < 32) {
                float* xn = (c & 1) ? xbuf0 : xbuf1;
                const float* src = xb + (t0 + 128);
                #pragma unroll
                for (int s = 0; s < 8; ++s) {
                    int u = tid + 256 * s;
                    int j = u >> 5, q = u & 31;
                    cp_async16(&xn[j * XSTR + q * 4], src + (size_t)j * DT + q * 4);
                }
                asm volatile("cp.async.commit_group;");
                asm volatile("cp.async.wait_group 1;");
            } else {
                asm volatile("cp.async.wait_group 0;");
            }
            __syncthreads();

            // mainloop: C[8 n-tiles][4]; B = X (fp32 in smem -> tf32 in reg)
            float C[8][4];
            #pragma unroll
            for (int t = 0; t < 8; ++t)
                C[t][0] = C[t][1] = C[t][2] = C[t][3] = 0.f;

            #pragma unroll
            for (int ks = 0; ks < 8; ++ks) {
                const float* b0r = &xc[(ks * 8 + tg)     * XSTR + nco + g];
                const float* b1r = &xc[(ks * 8 + tg + 4) * XSTR + nco + g];
                #pragma unroll
                for (int t = 0; t < 8; ++t) {
                    uint32_t b0 = f2tf32(b0r[t * 8]);    // single-phase LDS.32
                    uint32_t b1 = f2tf32(b1r[t * 8]);
                    mma_tf32(C[t][0], C[t][1], C[t][2], C[t][3],
                             A[ks][0], A[ks][1], A[ks][2], A[ks][3], b0, b1);
                }
            }

            // epilogue: add exact fp32 residual from smem, store
            #pragma unroll
            for (int t = 0; t < 8; ++t) {
                int lcol = nco + t * 8 + 2 * tg;
                float2 r0 = *(const float2*)&xc[(mw + g)     * XSTR + lcol];
                float2 r1 = *(const float2*)&xc[(mw + g + 8) * XSTR + lcol];
                *(float2*)(ob + (size_t)(mw + g)     * DT + t0 + lcol) =
                    make_float2(C[t][0] + r0.x, C[t][1] + r0.y);
                *(float2*)(ob + (size_t)(mw + g + 8) * DT + t0 + lcol) =
                    make_float2(C[t][2] + r1.x, C[t][3] + r1.y);
            }
            __syncthreads();   // compute(c) done before restaging this buffer
        }
    }
}

extern "C" void kernel_launch(void* const* d_in, const int* in_sizes, int n_in,
                              void* d_out, int out_size) {
    const float* x  = (const float*)d_in[0];
    const float* wq = (const float*)d_in[1];
    const float* bq = (const float*)d_in[2];
    const float* wk = (const float*)d_in[3];
    const float* bk = (const float*)d_in[4];
    float* out  = (float*)d_out;
    float* attn = out + (size_t)NBATCH * NN * DT;   // out tensor first, then attn

    cudaFuncSetAttribute(dga_fused, cudaFuncAttributeMaxDynamicSharedMemorySize,
                         SMEM_BYTES);
    dga_fused<<<NBATCH, THREADS, SMEM_BYTES>>>(x, wq, bq, wk, bk, out, attn);
}